// round 15
// baseline (speedup 1.0000x reference)
#include <cuda_runtime.h>
#include <cuda_bf16.h>
#include <cstddef>
#include <cstdint>

// Depthwise cross-correlation — R15: per-warp private double-buffered
// pipelines (NO __syncthreads anywhere), R12 compute kept verbatim.
//   out[ch, oy, ox] = sum_{ky,kx} x[ch, oy+ky, ox+kx] * z[ch, ky, kx]
//   32768 channels, x: 31x31, z: 7x7, out: 25x25 (VALID, no flip)
//
// Each warp owns a private SMEM slice and streams its own channel pairs with
// its own cp.async groups; the only sync is __syncwarp(). 12 warps/SM, one
// 384-thread CTA per SM (190KB smem forces 1 CTA/SM residency).

#define NCHAN   32768
#define NPAIR   (NCHAN / 2)         // 16384 channel pairs (1 per warp-step)
#define HX      31
#define HZ      7
#define HO      25
#define XSZ     961
#define ZSZ     49
#define OSZ     625
#define THREADS 384
#define WPC     12                  // warps per CTA
#define GRID    152                 // one CTA per SM
#define NWARPS  (GRID * WPC)        // 1824

#define XW      1928                // x floats per buffer: 2*961 + 6 pad (8B mult)
#define ZW      100                 // z floats per buffer: 2*49 + 2 pad (8B mult)
#define WBUF    (XW + ZW)           // 2028 floats per buffer
// per-warp: 2 buffers -> 16224 B; CTA total: 12 * 16224 = 194688 B

__device__ __forceinline__ void ffma2(float2& d, const float2& a, const float2& b) {
    asm("fma.rn.f32x2 %0, %1, %2, %0;"
        : "+l"(reinterpret_cast<unsigned long long&>(d))
        : "l"(reinterpret_cast<const unsigned long long&>(a)),
          "l"(reinterpret_cast<const unsigned long long&>(b)));
}

__device__ __forceinline__ void cpasync8(uint32_t saddr, const void* gaddr) {
    asm volatile("cp.async.ca.shared.global [%0], [%1], 8;"
                 :: "r"(saddr), "l"(gaddr) : "memory");
}
#define CP_COMMIT() asm volatile("cp.async.commit_group;" ::: "memory")
#define CP_WAIT1()  asm volatile("cp.async.wait_group 1;" ::: "memory")
#define CP_WAIT0()  asm volatile("cp.async.wait_group 0;" ::: "memory")

// Stage channel pair p into this warp's buffer (all 32 lanes, 8B chunks).
// x pair = 1922 floats = 961 8B chunks (base 8B-aligned for every p);
// z pair = 98 floats = 49 8B chunks.
__device__ __forceinline__ void prefetch_pair(
    int p, float* buf, const float* __restrict__ x,
    const float* __restrict__ z, int lane)
{
    const double* gx = reinterpret_cast<const double*>(x) + (size_t)p * XSZ; // 961 chunks
    const double* gz = reinterpret_cast<const double*>(z) + (size_t)p * ZSZ; // 49 chunks
    const uint32_t sx = (uint32_t)__cvta_generic_to_shared(buf);
    const uint32_t sz = (uint32_t)__cvta_generic_to_shared(buf + XW);
    #pragma unroll
    for (int j = lane; j < XSZ; j += 32)            // 30-31 per lane
        cpasync8(sx + (uint32_t)j * 8u, gx + j);
    #pragma unroll
    for (int j = lane; j < ZSZ; j += 32)            // 1-2 per lane
        cpasync8(sz + (uint32_t)j * 8u, gz + j);
}

// R12 compute, verbatim: f32x2 lanes = output columns (2l, 2l+1), dup taps,
// ring of 7 accumulators. Half-warp h handles channel 2p+h, lanes 0..12 active.
__device__ __forceinline__ void compute_pair(
    int p, const float* __restrict__ buf,
    float* __restrict__ out, int h, int l, bool active, bool store_hi)
{
    if (!active) return;

    const float* xc = buf + h * XSZ;
    const float* zc = buf + XW + h * ZSZ;
    const int col0 = 2 * l;

    float2 kt[ZSZ];
    #pragma unroll
    for (int j = 0; j < ZSZ; ++j) {
        const float zv = zc[j];
        kt[j] = make_float2(zv, zv);
    }

    float2 acc[HZ];
    #pragma unroll
    for (int i = 0; i < HZ; ++i) acc[i] = make_float2(0.0f, 0.0f);

    const float* xb = xc + col0;
    float* go = out + (size_t)(2 * p + h) * OSZ + col0;

    #pragma unroll
    for (int r = 0; r < HX; ++r) {
        // Lane 12 reads 1 float past its channel row-window (next channel /
        // pad); that value only feeds the dead .y lane of column 24.
        float w[8];
        #pragma unroll
        for (int c = 0; c < 8; ++c) w[c] = xb[r * HX + c];

        const float2 p0 = make_float2(w[0], w[1]);
        const float2 p1 = make_float2(w[2], w[3]);
        const float2 p2 = make_float2(w[4], w[5]);
        const float2 p3 = make_float2(w[6], w[7]);
        const float2 q0 = make_float2(w[1], w[2]);
        const float2 q1 = make_float2(w[3], w[4]);
        const float2 q2 = make_float2(w[5], w[6]);

        #pragma unroll
        for (int ky = 0; ky < HZ; ++ky) {
            const int oy = r - ky;
            if (oy >= 0 && oy < HO) {
                const int s = oy % HZ;
                const float2* kz = &kt[ky * HZ];
                ffma2(acc[s], p0, kz[0]);
                ffma2(acc[s], q0, kz[1]);
                ffma2(acc[s], p1, kz[2]);
                ffma2(acc[s], q1, kz[3]);
                ffma2(acc[s], p2, kz[4]);
                ffma2(acc[s], q2, kz[5]);
                ffma2(acc[s], p3, kz[6]);
            }
        }

        if (r >= HZ - 1) {
            const int oy = r - (HZ - 1);
            const int s  = oy % HZ;
            go[oy * HO] = acc[s].x;
            if (store_hi) go[oy * HO + 1] = acc[s].y;
            acc[s] = make_float2(0.0f, 0.0f);
        }
    }
}

__global__ __launch_bounds__(THREADS, 1)
void dwxcorr_warp(const float* __restrict__ z,
                  const float* __restrict__ x,
                  float* __restrict__ out) {
    extern __shared__ float smem[];

    const int tid  = threadIdx.x;
    const int warp = tid >> 5;
    const int lane = tid & 31;
    const int h    = lane >> 4;          // half-warp: channel within pair
    const int l    = lane & 15;          // lane within half-warp
    const bool active   = (l <= 12);     // 13 column-pair slots cover 25 cols
    const bool store_hi = (l < 12);      // lane 12: column 24 only

    float* buf0 = smem + warp * (2 * WBUF);
    float* buf1 = buf0 + WBUF;

    const int gwid = blockIdx.x * WPC + warp;   // global warp id

    int p = gwid;
    if (p < NPAIR)
        prefetch_pair(p, buf0, x, z, lane);
    CP_COMMIT();

    int i = 0;
    for (; p < NPAIR; p += NWARPS, ++i) {
        float* cur = (i & 1) ? buf1 : buf0;
        float* nxt = (i & 1) ? buf0 : buf1;

        const int pn = p + NWARPS;
        if (pn < NPAIR) {
            prefetch_pair(pn, nxt, x, z, lane);  // warp-private background fill
            CP_COMMIT();
            CP_WAIT1();                           // current pair landed
        } else {
            CP_WAIT0();
        }
        __syncwarp();                             // cross-lane smem visibility

        compute_pair(p, cur, out, h, l, active, store_hi);

        __syncwarp();                             // done reading cur
    }
}

extern "C" void kernel_launch(void* const* d_in, const int* in_sizes, int n_in,
                              void* d_out, int out_size) {
    // metadata order: d_in[0] = z_f [128,256,7,7], d_in[1] = x_f [128,256,31,31]
    const float* z = (const float*)d_in[0];
    const float* x = (const float*)d_in[1];
    float* out = (float*)d_out;

    const size_t smem = (size_t)WPC * 2 * WBUF * sizeof(float); // 194688 B
    cudaFuncSetAttribute(dwxcorr_warp,
                         cudaFuncAttributeMaxDynamicSharedMemorySize, (int)smem);
    cudaFuncSetAttribute(dwxcorr_warp,
                         cudaFuncAttributePreferredSharedMemoryCarveout, 100);
    dwxcorr_warp<<<GRID, THREADS, smem>>>(z, x, out);
}

// round 16
// speedup vs baseline: 1.1291x; 1.1291x over previous
#include <cuda_runtime.h>
#include <cuda_bf16.h>
#include <cstddef>
#include <cstdint>

// Depthwise cross-correlation — R16: R12 verbatim EXCEPT the inner loop nest
// is swapped to kx-outer / ky-inner so consecutive FFMA2s hit different ring
// slots (7 round-robin dependency chains instead of one 7-deep chain).
//   out[ch, oy, ox] = sum_{ky,kx} x[ch, oy+ky, ox+kx] * z[ch, ky, kx]
//   32768 channels, x: 31x31, z: 7x7, out: 25x25 (VALID, no flip)

#define NCHAN   32768
#define HX      31
#define HZ      7
#define HO      25
#define XSZ     961
#define ZSZ     49
#define OSZ     625
#define CPG     8               // channels per group (2 per warp)
#define THREADS 128
#define CTAS_PER_SM 3
#define GRID    (152 * CTAS_PER_SM)   // 456
#define NGROUPS (NCHAN / CPG)         // 4096 exactly

#define GX_FLOATS (CPG * XSZ)         // 7688 (30752 B, 16B-multiple)
#define GX_PAD    (GX_FLOATS + 4)     // +4: lane-12 window overrun slack
#define GZ_FLOATS (CPG * ZSZ)         // 392 (1568 B, 16B-multiple)
#define GX_V4     (GX_FLOATS / 4)     // 1922
#define GZ_V4     (GZ_FLOATS / 4)     // 98

__device__ __forceinline__ void ffma2(float2& d, const float2& a, const float2& b) {
    asm("fma.rn.f32x2 %0, %1, %2, %0;"
        : "+l"(reinterpret_cast<unsigned long long&>(d))
        : "l"(reinterpret_cast<const unsigned long long&>(a)),
          "l"(reinterpret_cast<const unsigned long long&>(b)));
}

__device__ __forceinline__ void cpasync16(uint32_t saddr, const void* gaddr) {
    asm volatile("cp.async.cg.shared.global [%0], [%1], 16;"
                 :: "r"(saddr), "l"(gaddr) : "memory");
}
#define CP_COMMIT() asm volatile("cp.async.commit_group;" ::: "memory")
#define CP_WAIT1()  asm volatile("cp.async.wait_group 1;" ::: "memory")
#define CP_WAIT0()  asm volatile("cp.async.wait_group 0;" ::: "memory")

__device__ __forceinline__ void prefetch_group(
    int g, float* xs, float* zs,
    const float* __restrict__ x, const float* __restrict__ z, int tid)
{
    const float4* gx = reinterpret_cast<const float4*>(x) + (size_t)g * GX_V4;
    const float4* gz = reinterpret_cast<const float4*>(z) + (size_t)g * GZ_V4;
    const uint32_t sx = (uint32_t)__cvta_generic_to_shared(xs);
    const uint32_t sz = (uint32_t)__cvta_generic_to_shared(zs);
    #pragma unroll
    for (int j = tid; j < GX_V4; j += THREADS)     // ~15 per thread
        cpasync16(sx + (uint32_t)j * 16u, gx + j);
    if (tid < GZ_V4)
        cpasync16(sz + (uint32_t)tid * 16u, gz + tid);
}

__device__ __forceinline__ void compute_group(
    int g, const float* __restrict__ xs, const float* __restrict__ zs,
    float* __restrict__ out, int lch, int l, bool active, bool store_hi)
{
    if (!active) return;                 // lanes 13..15 of each half-warp idle

    const float* xc = xs + lch * XSZ;
    const float* zc = zs + lch * ZSZ;
    const int col0 = 2 * l;              // output columns (col0, col0+1)

    // Taps duplicated into both f32x2 lanes: 49 float2 (98 regs), broadcast LDS.
    float2 kt[ZSZ];
    #pragma unroll
    for (int j = 0; j < ZSZ; ++j) {
        const float zv = zc[j];
        kt[j] = make_float2(zv, zv);
    }

    // Ring of 7 accumulators; lanes = the two adjacent output columns.
    float2 acc[HZ];
    #pragma unroll
    for (int i = 0; i < HZ; ++i) acc[i] = make_float2(0.0f, 0.0f);

    const float* xb = xc + col0;
    float* go = out + (size_t)(g * CPG + lch) * OSZ + col0;

    #pragma unroll
    for (int r = 0; r < HX; ++r) {
        // 8-float window serves both output columns. Lane l=12 reads one float
        // past the row (next row / +4 pad) into w[7]; its .y result is dropped.
        float w[8];
        #pragma unroll
        for (int c = 0; c < 8; ++c) w[c] = xb[r * HX + c];

        // Multiplicand pairs m[j] <-> tap column kx=j.
        float2 m[HZ];
        m[0] = make_float2(w[0], w[1]);   // even pairs: free
        m[2] = make_float2(w[2], w[3]);
        m[4] = make_float2(w[4], w[5]);
        m[6] = make_float2(w[6], w[7]);
        m[1] = make_float2(w[1], w[2]);   // odd pairs: MOV-built
        m[3] = make_float2(w[3], w[4]);
        m[5] = make_float2(w[5], w[6]);

        // kx-OUTER / ky-INNER: consecutive ffma2 target different ring slots
        // (oy = r-ky), so the 7 accumulator chains interleave round-robin.
        #pragma unroll
        for (int kx = 0; kx < HZ; ++kx) {
            #pragma unroll
            for (int ky = 0; ky < HZ; ++ky) {
                const int oy = r - ky;
                if (oy >= 0 && oy < HO) {
                    const int s = oy % HZ;          // const after unroll
                    ffma2(acc[s], m[kx], kt[ky * HZ + kx]);
                }
            }
        }

        if (r >= HZ - 1) {                           // output row r-6 complete
            const int oy = r - (HZ - 1);
            const int s  = oy % HZ;
            go[oy * HO] = acc[s].x;
            if (store_hi) go[oy * HO + 1] = acc[s].y;
            acc[s] = make_float2(0.0f, 0.0f);
        }
    }
}

__global__ __launch_bounds__(THREADS, CTAS_PER_SM)
void dwxcorr_ilp(const float* __restrict__ z,
                 const float* __restrict__ x,
                 float* __restrict__ out) {
    extern __shared__ float smem[];
    float* xb0 = smem;
    float* xb1 = smem + GX_PAD;
    float* zb0 = smem + 2 * GX_PAD;
    float* zb1 = zb0 + GZ_FLOATS;

    const int tid  = threadIdx.x;
    const int warp = tid >> 5;
    const int lane = tid & 31;
    const int h    = lane >> 4;          // half-warp: channel select
    const int l    = lane & 15;          // lane within half-warp
    const int lch  = 2 * warp + h;       // local channel 0..7
    const bool active   = (l <= 12);     // 13 column-pair slots cover 25 cols
    const bool store_hi = (l < 12);      // lane 12: column 24 only

    int g = blockIdx.x;
    if (g < NGROUPS)
        prefetch_group(g, xb0, zb0, x, z, tid);
    CP_COMMIT();

    int i = 0;
    for (; g < NGROUPS; g += GRID, ++i) {
        float* xc = (i & 1) ? xb1 : xb0;
        float* zc = (i & 1) ? zb1 : zb0;
        float* xn = (i & 1) ? xb0 : xb1;
        float* zn = (i & 1) ? zb0 : zb1;

        const int gn = g + GRID;
        if (gn < NGROUPS) {
            prefetch_group(gn, xn, zn, x, z, tid);   // background fill
            CP_COMMIT();
            CP_WAIT1();                               // current group landed
        } else {
            CP_WAIT0();
        }
        __syncthreads();

        compute_group(g, xc, zc, out, lch, l, active, store_hi);

        __syncthreads();                              // done reading xc/zc
    }
}

extern "C" void kernel_launch(void* const* d_in, const int* in_sizes, int n_in,
                              void* d_out, int out_size) {
    // metadata order: d_in[0] = z_f [128,256,7,7], d_in[1] = x_f [128,256,31,31]
    const float* z = (const float*)d_in[0];
    const float* x = (const float*)d_in[1];
    float* out = (float*)d_out;

    const size_t smem = (size_t)(2 * GX_PAD + 2 * GZ_FLOATS) * sizeof(float); // 64672 B
    cudaFuncSetAttribute(dwxcorr_ilp,
                         cudaFuncAttributeMaxDynamicSharedMemorySize, (int)smem);
    dwxcorr_ilp<<<GRID, THREADS, smem>>>(z, x, out);
}